// round 12
// baseline (speedup 1.0000x reference)
#include <cuda_runtime.h>
#include <cuda_bf16.h>

// Problem constants (fixed by the dataset)
#define NN   2048   // nodes
#define ZD   64     // z_dim
#define HID  64     // hidden
#define TJB  256    // j-columns per block
#define TB   128    // threads per block (each owns 2 j's: t and t+128)
#define RI   8      // i-rows per block (packed accumulators)
#define NPB  4      // nodes per block in stage 1
#define KH   32     // k's per smem-staged half
#define QH   (KH/4) // quads per half = 8

// Scratch (allocation-free rule: __device__ globals)
__device__ float    g_PI [NN * HID]; // pi'[n][h] = w2[h]*(z@W1[:ZD] + b1)  (row-major)
__device__ float    g_PJ4[HID * NN]; // pj'^T quad-interleaved: [(h>>2)][n][h&3], w2-scaled
__device__ float    g_A  [NN];       // a_i = sum_k w2[k]*(pi[i,k]+b1[k])
__device__ float    g_B  [NN];       // b_j = sum_k w2[k]*pj[j,k]
__device__ unsigned g_SGN[HID];      // signbit(w2[k]) << 31

// sm_103a packed fp32 add (FADD2-class, fma pipe, rt=2 — no 3-operand bank penalty)
#define F32X2_ADD(d, a, b) \
    asm("add.rn.f32x2 %0, %1, %2;" : "=l"(d) : "l"(a), "l"(b))

// ---------------------------------------------------------------------------
// Stage 1: w2-scaled projections + rank-1 terms + w2 sign masks.
//   half 0 (t<64):  pi'[n][h] = w2[h]*(z[n]@W1[:ZD,h] + b1[h]) -> g_PI
//   half 1 (t>=64): pj'[n][h] = w2[h]* z[n]@W1[ZD:,h]          -> g_PJ4
// a[n] = sum_h pi'[n][h], b[n] = sum_h pj'[n][h] via shuffle reduce.
// ---------------------------------------------------------------------------
__global__ void edge_proj_kernel(const float* __restrict__ z,
                                 const float* __restrict__ W1,
                                 const float* __restrict__ b1,
                                 const float* __restrict__ W2) {
    __shared__ float zs[ZD];
    __shared__ float red[4];
    const int t    = threadIdx.x;            // 0..127
    const int half = t >> 6;
    const int h    = t & 63;
    const float* w  = W1 + (half * ZD) * HID + h;
    const float b1v = b1[h];
    const float w2v = W2[h];

    if (blockIdx.x == 0 && t < HID)          // t<64 -> h==t
        g_SGN[t] = __float_as_uint(w2v) & 0x80000000u;

    for (int rep = 0; rep < NPB; rep++) {
        const int n = blockIdx.x * NPB + rep;
        if (t < ZD) zs[t] = z[n * ZD + t];
        __syncthreads();

        float acc = 0.f;
        #pragma unroll
        for (int d = 0; d < ZD; d++)
            acc = fmaf(zs[d], w[d * HID], acc);   // W1 L1-resident after rep 0

        // w2-scaled value (sign-fold trick): store pi' / pj'
        const float val = ((half == 0) ? (acc + b1v) : acc) * w2v;
        if (half == 0) g_PI [n * HID + h] = val;
        else           g_PJ4[(h >> 2) * (4 * NN) + 4 * n + (h & 3)] = val;

        // fused a/b reduction (a = sum pi', b = sum pj')
        float v = val;
        #pragma unroll
        for (int off = 16; off; off >>= 1)
            v += __shfl_down_sync(0xffffffffu, v, off);
        if ((t & 31) == 0) red[t >> 5] = v;
        __syncthreads();
        if (t == 0)  g_A[n] = red[0] + red[1];
        if (t == 64) g_B[n] = red[2] + red[3];
        __syncthreads();
    }
}

// ---------------------------------------------------------------------------
// Stage 2: pairwise core via sign-folding:
//   sum_k w2*relu(s) = 0.5*(a_i + b_j + sum_k sign(w2_k)*|pi'+pj'|)
// Per packed unit (2 k's): add.rn.f32x2 (rt2) + 2x LOP3 ((s&ABS)|sgn, one op
// does abs AND sign-fold) + add.rn.f32x2 (rt2). No FFMA2 -> no rt=3 RF-bank
// penalty on the fma pipe (R11 evidence: issue capped ~60% by FFMA2).
// pj' staged via smem in two 32KB halves; steady loop has no global loads.
// ---------------------------------------------------------------------------
__global__ void __launch_bounds__(TB, 6)
edge_pair_kernel(const float* __restrict__ b2,
                 float* __restrict__ out) {
    __shared__ __align__(16) float4   s_pj[QH * TJB]; // 32KB: one k-half
    __shared__ __align__(16) float    s_pi[RI * HID]; // 2KB
    __shared__ __align__(16) unsigned s_sgn[HID];     // per-k sign masks
    __shared__ float s_lin[RI];

    const int t  = threadIdx.x;                     // 0..127
    const int j0 = blockIdx.x * TJB;
    const int i0 = blockIdx.y * RI;

    #pragma unroll
    for (int idx = t; idx < RI * HID; idx += TB)
        s_pi[idx] = g_PI[i0 * HID + idx];
    if (t < HID) s_sgn[t] = g_SGN[t];
    if (t < RI)  s_lin[t] = g_A[i0 + t];

    unsigned long long acc0[RI], acc1[RI];
    #pragma unroll
    for (int i = 0; i < RI; i++) { acc0[i] = 0ULL; acc1[i] = 0ULL; }

    const unsigned long long ABSM = 0x7fffffff7fffffffULL;

    #pragma unroll 1
    for (int hf = 0; hf < 2; hf++) {
        if (hf) __syncthreads();   // all reads of previous half complete

        // Cooperative fill: quad Q = hf*QH + q of j-range [j0, j0+256).
        {
            const float4* src = reinterpret_cast<const float4*>(
                                    &g_PJ4[(hf * QH) * (4 * NN) + 4 * j0]);
            #pragma unroll
            for (int q = 0; q < QH; q++) {
                s_pj[q * TJB + t      ] = src[q * NN + t      ];
                s_pj[q * TJB + t + TB ] = src[q * NN + t + TB ];
            }
        }
        __syncthreads();   // (also covers s_pi/s_sgn/s_lin fills when hf==0)

        #pragma unroll
        for (int c = 0; c < KH / 8; c++) {            // 4 chunks of 8 k's
            // ---- hoisted chunk loads (6 LDS.128) ----
            const ulonglong2 pA0 = *reinterpret_cast<const ulonglong2*>(
                                       &s_pj[(2 * c + 0) * TJB + t]);
            const ulonglong2 pB0 = *reinterpret_cast<const ulonglong2*>(
                                       &s_pj[(2 * c + 1) * TJB + t]);
            const ulonglong2 pA1 = *reinterpret_cast<const ulonglong2*>(
                                       &s_pj[(2 * c + 0) * TJB + t + TB]);
            const ulonglong2 pB1 = *reinterpret_cast<const ulonglong2*>(
                                       &s_pj[(2 * c + 1) * TJB + t + TB]);
            // sign masks for this chunk's 4 k-pairs (broadcast LDS.128)
            const ulonglong2 m2 = *reinterpret_cast<const ulonglong2*>(
                                      &s_sgn[hf * KH + 8 * c]);
            const ulonglong2 m3 = *reinterpret_cast<const ulonglong2*>(
                                      &s_sgn[hf * KH + 8 * c + 4]);
            const unsigned long long mAx = m2.x, mAy = m2.y;
            const unsigned long long mBx = m3.x, mBy = m3.y;

            #pragma unroll
            for (int i = 0; i < RI; i++) {
                const ulonglong2* pp = reinterpret_cast<const ulonglong2*>(
                                           &s_pi[i * HID + hf * KH + 8 * c]);
                const ulonglong2 a0 = pp[0];          // broadcast LDS.128
                const ulonglong2 a1 = pp[1];          // shared by both jr's

                // Phase 1: 8 independent packed ADDs (fma pipe, rt2)
                unsigned long long s00, s01, s02, s03, s10, s11, s12, s13;
                F32X2_ADD(s00, a0.x, pA0.x);
                F32X2_ADD(s10, a0.x, pA1.x);
                F32X2_ADD(s01, a0.y, pA0.y);
                F32X2_ADD(s11, a0.y, pA1.y);
                F32X2_ADD(s02, a1.x, pB0.x);
                F32X2_ADD(s12, a1.x, pB1.x);
                F32X2_ADD(s03, a1.y, pB0.y);
                F32X2_ADD(s13, a1.y, pB1.y);
                // Phase 2: abs + sign-fold in ONE LOP3 per 32-bit half (alu)
                s00 = (s00 & ABSM) | mAx;  s10 = (s10 & ABSM) | mAx;
                s01 = (s01 & ABSM) | mAy;  s11 = (s11 & ABSM) | mAy;
                s02 = (s02 & ABSM) | mBx;  s12 = (s12 & ABSM) | mBx;
                s03 = (s03 & ABSM) | mBy;  s13 = (s13 & ABSM) | mBy;
                // Phase 3: 8 packed accumulate ADDs (fma pipe, rt2);
                // acc0/acc1 chains interleaved (dep distance 2)
                F32X2_ADD(acc0[i], acc0[i], s00);
                F32X2_ADD(acc1[i], acc1[i], s10);
                F32X2_ADD(acc0[i], acc0[i], s01);
                F32X2_ADD(acc1[i], acc1[i], s11);
                F32X2_ADD(acc0[i], acc0[i], s02);
                F32X2_ADD(acc1[i], acc1[i], s12);
                F32X2_ADD(acc0[i], acc0[i], s03);
                F32X2_ADD(acc1[i], acc1[i], s13);
            }
        }
    }

    const float b2v = b2[0];
    const float bj0 = g_B[j0 + t];
    const float bj1 = g_B[j0 + t + TB];
    #pragma unroll
    for (int i = 0; i < RI; i++) {
        const float lo0 = __uint_as_float((unsigned)(acc0[i] & 0xffffffffULL));
        const float hi0 = __uint_as_float((unsigned)(acc0[i] >> 32));
        const float x0  = fmaf(0.5f, s_lin[i] + bj0 + (lo0 + hi0), b2v);
        out[(i0 + i) * NN + j0 + t     ] = 1.0f / (1.0f + __expf(-x0));
        const float lo1 = __uint_as_float((unsigned)(acc1[i] & 0xffffffffULL));
        const float hi1 = __uint_as_float((unsigned)(acc1[i] >> 32));
        const float x1  = fmaf(0.5f, s_lin[i] + bj1 + (lo1 + hi1), b2v);
        out[(i0 + i) * NN + j0 + t + TB] = 1.0f / (1.0f + __expf(-x1));
    }
}

// ---------------------------------------------------------------------------
// Inputs per metadata order: z, W1, b1, W2, b2. Output: float32 [2048*2048].
// Graph-capturable: two launches, no sync, no allocation.
// ---------------------------------------------------------------------------
extern "C" void kernel_launch(void* const* d_in, const int* in_sizes, int n_in,
                              void* d_out, int out_size) {
    const float* z  = (const float*)d_in[0];
    const float* W1 = (const float*)d_in[1];
    const float* b1 = (const float*)d_in[2];
    const float* W2 = (const float*)d_in[3];
    const float* b2 = (const float*)d_in[4];
    float* out = (float*)d_out;

    edge_proj_kernel<<<NN / NPB, 128>>>(z, W1, b1, W2);

    dim3 grid(NN / TJB, NN / RI);
    edge_pair_kernel<<<grid, TB>>>(b2, out);
}

// round 16
// speedup vs baseline: 1.0416x; 1.0416x over previous
#include <cuda_runtime.h>
#include <cuda_bf16.h>

// Problem constants (fixed by the dataset)
#define NN   2048   // nodes
#define ZD   64     // z_dim
#define HID  64     // hidden
#define TJB  256    // j-columns per block
#define TB   128    // threads per block (each owns 2 j's: t and t+128)
#define RI   4      // i-rows per block (16 acc regs -> 7 blocks/SM)
#define NPB  4      // nodes per block in stage 1
#define KH   16     // k's per smem-staged half (16KB tile -> 7 blocks/SM)
#define QH   (KH/4) // quads per half = 4
#define NHF  (HID/KH) // 4 halves

// Scratch (allocation-free rule: __device__ globals)
__device__ float g_PI [NN * HID];   // pi[n][h] = z@W1[:ZD] + b1  (row-major)
__device__ float g_PJ4[HID * NN];   // pj^T quad-interleaved: [(h>>2)][n][h&3]
__device__ float g_A  [NN];         // a_i = sum_k pi[i,k] * w2[k]
__device__ float g_B  [NN];         // b_j = sum_k pj[j,k] * w2[k]

// sm_103a packed fp32 ops (fma pipe)
#define F32X2_ADD(d, a, b) \
    asm("add.rn.f32x2 %0, %1, %2;" : "=l"(d) : "l"(a), "l"(b))
#define F32X2_FMA(d, a, b, c) \
    asm("fma.rn.f32x2 %0, %1, %2, %3;" : "=l"(d) : "l"(a), "l"(b), "l"(c))

// ---------------------------------------------------------------------------
// Stage 1: projections + rank-1 terms (R11 version, unchanged).
// ---------------------------------------------------------------------------
__global__ void edge_proj_kernel(const float* __restrict__ z,
                                 const float* __restrict__ W1,
                                 const float* __restrict__ b1,
                                 const float* __restrict__ W2) {
    __shared__ float zs[ZD];
    __shared__ float red[4];
    const int t    = threadIdx.x;            // 0..127
    const int half = t >> 6;
    const int h    = t & 63;
    const float* w  = W1 + (half * ZD) * HID + h;
    const float b1v = b1[h];
    const float w2v = W2[h];

    for (int rep = 0; rep < NPB; rep++) {
        const int n = blockIdx.x * NPB + rep;
        if (t < ZD) zs[t] = z[n * ZD + t];
        __syncthreads();

        float acc = 0.f;
        #pragma unroll
        for (int d = 0; d < ZD; d++)
            acc = fmaf(zs[d], w[d * HID], acc);

        const float val = (half == 0) ? (acc + b1v) : acc;
        if (half == 0) g_PI [n * HID + h] = val;
        else           g_PJ4[(h >> 2) * (4 * NN) + 4 * n + (h & 3)] = val;

        float v = val * w2v;
        #pragma unroll
        for (int off = 16; off; off >>= 1)
            v += __shfl_down_sync(0xffffffffu, v, off);
        if ((t & 31) == 0) red[t >> 5] = v;
        __syncthreads();
        if (t == 0)  g_A[n] = red[0] + red[1];
        if (t == 64) g_B[n] = red[2] + red[3];
        __syncthreads();
    }
}

// ---------------------------------------------------------------------------
// Stage 2: pairwise core (R11 math: relu via (x+|x|)/2, packed f32x2).
// R13 delta: RI=4 + KH=16 to cut regs (~70) and smem (~19KB) -> 7 blocks/SM
// (28 warps) for latency coverage; grid 4096 for a smaller tail fraction.
// Phase temps s0..s3 reused across jr (dep distance 4 >= cross-pipe RAW 5
// at multi-warp).
// ---------------------------------------------------------------------------
__global__ void __launch_bounds__(TB, 7)
edge_pair_kernel(const float* __restrict__ W2,
                 const float* __restrict__ b2,
                 float* __restrict__ out) {
    __shared__ __align__(16) float4 s_pj[QH * TJB]; // 16KB: one k-half
    __shared__ __align__(16) float  s_pi[RI * HID]; // 1KB
    __shared__ __align__(16) float  s_w2[HID];
    __shared__ float s_lin[RI];

    const int t  = threadIdx.x;                     // 0..127
    const int j0 = blockIdx.x * TJB;
    const int i0 = blockIdx.y * RI;

    #pragma unroll
    for (int idx = t; idx < RI * HID; idx += TB)
        s_pi[idx] = g_PI[i0 * HID + idx];
    if (t < HID) s_w2[t] = W2[t];
    if (t < RI)  s_lin[t] = g_A[i0 + t];

    unsigned long long acc0[RI], acc1[RI];
    #pragma unroll
    for (int i = 0; i < RI; i++) { acc0[i] = 0ULL; acc1[i] = 0ULL; }

    const unsigned long long ABSM = 0x7fffffff7fffffffULL;

    #pragma unroll 1
    for (int hf = 0; hf < NHF; hf++) {
        if (hf) __syncthreads();   // all reads of previous half complete

        // Cooperative fill: quad Q = hf*QH + q of j-range [j0, j0+256).
        {
            const float4* src = reinterpret_cast<const float4*>(
                                    &g_PJ4[(hf * QH) * (4 * NN) + 4 * j0]);
            #pragma unroll
            for (int q = 0; q < QH; q++) {
                s_pj[q * TJB + t      ] = src[q * NN + t      ];
                s_pj[q * TJB + t + TB ] = src[q * NN + t + TB ];
            }
        }
        __syncthreads();   // (also covers s_pi/s_w2/s_lin fills when hf==0)

        #pragma unroll
        for (int c = 0; c < KH / 8; c++) {            // 2 chunks of 8 k's
            // ---- hoisted chunk loads (6 LDS.128) ----
            const ulonglong2 pA0 = *reinterpret_cast<const ulonglong2*>(
                                       &s_pj[(2 * c + 0) * TJB + t]);
            const ulonglong2 pB0 = *reinterpret_cast<const ulonglong2*>(
                                       &s_pj[(2 * c + 1) * TJB + t]);
            const ulonglong2 pA1 = *reinterpret_cast<const ulonglong2*>(
                                       &s_pj[(2 * c + 0) * TJB + t + TB]);
            const ulonglong2 pB1 = *reinterpret_cast<const ulonglong2*>(
                                       &s_pj[(2 * c + 1) * TJB + t + TB]);
            const ulonglong2* w2q = reinterpret_cast<const ulonglong2*>(
                                        &s_w2[hf * KH + 8 * c]);
            const ulonglong2 wA = w2q[0];
            const ulonglong2 wB = w2q[1];

            #pragma unroll
            for (int i = 0; i < RI; i++) {
                const ulonglong2* pp = reinterpret_cast<const ulonglong2*>(
                                           &s_pi[i * HID + hf * KH + 8 * c]);
                const ulonglong2 a0 = pp[0];          // broadcast LDS.128
                const ulonglong2 a1 = pp[1];          // shared by both jr's

                unsigned long long s0, s1, s2, s3;
                // jr = 0: phases ADD -> LOP3 -> FMA (dep distance 4)
                F32X2_ADD(s0, a0.x, pA0.x);
                F32X2_ADD(s1, a0.y, pA0.y);
                F32X2_ADD(s2, a1.x, pB0.x);
                F32X2_ADD(s3, a1.y, pB0.y);
                s0 &= ABSM; s1 &= ABSM; s2 &= ABSM; s3 &= ABSM;
                F32X2_FMA(acc0[i], s0, wA.x, acc0[i]);
                F32X2_FMA(acc0[i], s1, wA.y, acc0[i]);
                F32X2_FMA(acc0[i], s2, wB.x, acc0[i]);
                F32X2_FMA(acc0[i], s3, wB.y, acc0[i]);
                // jr = 1
                F32X2_ADD(s0, a0.x, pA1.x);
                F32X2_ADD(s1, a0.y, pA1.y);
                F32X2_ADD(s2, a1.x, pB1.x);
                F32X2_ADD(s3, a1.y, pB1.y);
                s0 &= ABSM; s1 &= ABSM; s2 &= ABSM; s3 &= ABSM;
                F32X2_FMA(acc1[i], s0, wA.x, acc1[i]);
                F32X2_FMA(acc1[i], s1, wA.y, acc1[i]);
                F32X2_FMA(acc1[i], s2, wB.x, acc1[i]);
                F32X2_FMA(acc1[i], s3, wB.y, acc1[i]);
            }
        }
    }

    const float b2v = b2[0];
    const float bj0 = g_B[j0 + t];
    const float bj1 = g_B[j0 + t + TB];
    #pragma unroll
    for (int i = 0; i < RI; i++) {
        const float lo0 = __uint_as_float((unsigned)(acc0[i] & 0xffffffffULL));
        const float hi0 = __uint_as_float((unsigned)(acc0[i] >> 32));
        const float x0  = fmaf(0.5f, s_lin[i] + bj0 + (lo0 + hi0), b2v);
        out[(i0 + i) * NN + j0 + t     ] = 1.0f / (1.0f + __expf(-x0));
        const float lo1 = __uint_as_float((unsigned)(acc1[i] & 0xffffffffULL));
        const float hi1 = __uint_as_float((unsigned)(acc1[i] >> 32));
        const float x1  = fmaf(0.5f, s_lin[i] + bj1 + (lo1 + hi1), b2v);
        out[(i0 + i) * NN + j0 + t + TB] = 1.0f / (1.0f + __expf(-x1));
    }
}

// ---------------------------------------------------------------------------
// Inputs per metadata order: z, W1, b1, W2, b2. Output: float32 [2048*2048].
// Graph-capturable: two launches, no sync, no allocation.
// ---------------------------------------------------------------------------
extern "C" void kernel_launch(void* const* d_in, const int* in_sizes, int n_in,
                              void* d_out, int out_size) {
    const float* z  = (const float*)d_in[0];
    const float* W1 = (const float*)d_in[1];
    const float* b1 = (const float*)d_in[2];
    const float* W2 = (const float*)d_in[3];
    const float* b2 = (const float*)d_in[4];
    float* out = (float*)d_out;

    edge_proj_kernel<<<NN / NPB, 128>>>(z, W1, b1, W2);

    dim3 grid(NN / TJB, NN / RI);
    edge_pair_kernel<<<grid, TB>>>(W2, b2, out);
}